// round 16
// baseline (speedup 1.0000x reference)
#include <cuda_runtime.h>
#include <math.h>

#define NMAX 16000
#define EMAX 256000

// ---------------- static device scratch ----------------
__device__ float g_xvT [3*NMAX*64];
__device__ float g_f0  [NMAX*192];
__device__ float g_pre_s[NMAX*128];
__device__ float g_pre_v[3*NMAX*64];
__device__ float g_h1  [NMAX*192];
__device__ float g_g   [NMAX*192];
__device__ float g_xv2T[3*NMAX*64];
__device__ float g_xs3 [NMAX*128];
__device__ float g_xv3 [3*NMAX*64];
__device__ float g_ns  [NMAX*192];
__device__ float g_nv  [3*NMAX*192];
__device__ float g_nl1 [NMAX*32];
__device__ float g_Wl1c[128*32];
__device__ int   g_ei  [2*EMAX];

// ---------------- fused setup: convert + prep + wsum + zero ----------------
// All four are independent of every GEMM. zero targets g_ns/g_nv (written only
// by edge kernel); wsum needs only Wl1. One launch replaces four.
__global__ void setup_kernel(const int* __restrict__ ei_raw,
                             const float* __restrict__ x,
                             const float* __restrict__ Wl1,
                             int N, int E) {
    __shared__ int s_is64;
    if (threadIdx.x == 0) {
        int nz = 0;
        for (int i = 1; i < 256; i += 2) nz += (ei_raw[i] != 0);
        s_is64 = (nz == 0) ? 1 : 0;
    }
    __syncthreads();
    int is64 = s_is64;

    int tc = 2 * E;                       // [0, tc): edge index convert
    int tp = tc + N * 192;                // [tc, tp): prep
    int tw = tp + 128 * 32;               // [tp, tw): wsum
    int tz = tw + N * 192 + 3 * N * 192;  // [tw, tz): zero ns/nv

    for (int idx = blockIdx.x * blockDim.x + threadIdx.x; idx < tz;
         idx += gridDim.x * blockDim.x) {
        if (idx < tc) {
            g_ei[idx] = is64 ? ei_raw[2 * idx] : ei_raw[idx];
        } else if (idx < tp) {
            int r = idx - tc;
            int n = r / 192, i = r - n * 192;
            if (i < 128) {
                g_f0[n * 192 + i] = x[n * 320 + i];
            } else {
                int u = i - 128;
                float a = x[n * 320 + 128 + 3 * u + 0];
                float b = x[n * 320 + 128 + 3 * u + 1];
                float c = x[n * 320 + 128 + 3 * u + 2];
                g_xvT[(0 * N + n) * 64 + u] = a;
                g_xvT[(1 * N + n) * 64 + u] = b;
                g_xvT[(2 * N + n) * 64 + u] = c;
                g_f0[n * 192 + i] = sqrtf(a * a + b * b + c * c + 1e-12f);
            }
        } else if (idx < tw) {
            int i = idx - tp;
            g_Wl1c[i] = Wl1[i] + Wl1[128 * 32 + i];
        } else {
            int i = idx - tw;
            if (i < N * 192) g_ns[i] = 0.f;
            else             g_nv[i - N * 192] = 0.f;
        }
    }
}

__global__ void gate_kernel(int N) {
    int total = 3 * N * 64;
    for (int idx = blockIdx.x * blockDim.x + threadIdx.x; idx < total;
         idx += gridDim.x * blockDim.x) {
        int rem = idx % (N * 64);
        int n = rem / 64, u = rem - n * 64;
        g_xv2T[idx] = g_xvT[idx] * g_g[n * 192 + 128 + u];
    }
}

__global__ void nl1_kernel(int N) {
    __shared__ float sW[128 * 32];
    int tid = threadIdx.x;
    for (int i = tid; i < 128 * 32; i += 256) sW[i] = g_Wl1c[i];
    __syncthreads();
    int j = tid & 31;
    int n = blockIdx.x * 8 + (tid >> 5);
    if (n >= N) return;
    const float* row = &g_pre_s[(size_t)n * 128];
    float acc = 0.f;
#pragma unroll 8
    for (int q = 0; q < 128; q++) acc += row[q] * sW[q * 32 + j];
    g_nl1[(size_t)n * 32 + j] = acc;
}

// ---------------- cp.async helpers ----------------
__device__ __forceinline__ void cp_async4(unsigned saddr, const float* gptr) {
    asm volatile("cp.async.ca.shared.global [%0], [%1], 4;" :: "r"(saddr), "l"(gptr));
}
__device__ __forceinline__ void cp_commit() {
    asm volatile("cp.async.commit_group;" ::: "memory");
}
__device__ __forceinline__ void cp_wait1() {
    asm volatile("cp.async.wait_group 1;" ::: "memory");
}
__device__ __forceinline__ void cp_wait0() {
    asm volatile("cp.async.wait_group 0;" ::: "memory");
}

// ---------------- multi-job SGEMM, flat 1D grid, cp.async double-buffered ----------------
struct GemmJob {
    const float* X; const float* W; float* C; const float* bias;
    int ldx, ldw, ldc;
    int K;
    float scale;
    int act, out_mode, nnodes;
    int gx, gy, off;
};

__device__ __forceinline__ void gemm_body(const GemmJob& jb, int bx, int by) {
    __shared__ __align__(16) float sX[2][16][132];
    __shared__ __align__(16) float sW[2][16][68];
    int bm = by * 128, bo = bx * 64;
    int tid = threadIdx.x;
    int tr = tid >> 4, tc = tid & 15;
    int m0 = tr * 8, o0 = tc * 4;

    float acc[8][4];
#pragma unroll
    for (int i = 0; i < 8; i++)
#pragma unroll
        for (int j = 0; j < 4; j++) acc[i][j] = 0.f;

    unsigned sxa[8], swa[4];
    int gxo[8], gwo[4];
#pragma unroll
    for (int l = 0; l < 8; l++) {
        int i = tid + l * 256;
        int r = i >> 4, c = i & 15;
        sxa[l] = (unsigned)__cvta_generic_to_shared(&sX[0][c][r]);
        gxo[l] = (bm + r) * jb.ldx + c;
    }
#pragma unroll
    for (int l = 0; l < 4; l++) {
        int i = tid + l * 256;
        int r = i >> 6, c = i & 63;
        swa[l] = (unsigned)__cvta_generic_to_shared(&sW[0][r][c]);
        gwo[l] = r * jb.ldw + bo + c;
    }
    const unsigned SXB = 16 * 132 * 4;
    const unsigned SWB = 16 * 68 * 4;

    int ntiles = jb.K >> 4;
#pragma unroll
    for (int l = 0; l < 8; l++) cp_async4(sxa[l], jb.X + gxo[l]);
#pragma unroll
    for (int l = 0; l < 4; l++) cp_async4(swa[l], jb.W + gwo[l]);
    cp_commit();

    for (int t = 0; t < ntiles; t++) {
        if (t + 1 < ntiles) {
            int k0 = (t + 1) << 4;
            unsigned bofX = ((t + 1) & 1) ? SXB : 0u;
            unsigned bofW = ((t + 1) & 1) ? SWB : 0u;
            int wstep = k0 * jb.ldw;
#pragma unroll
            for (int l = 0; l < 8; l++)
                cp_async4(sxa[l] + bofX, jb.X + gxo[l] + k0);
#pragma unroll
            for (int l = 0; l < 4; l++)
                cp_async4(swa[l] + bofW, jb.W + gwo[l] + wstep);
            cp_commit();
            cp_wait1();
        } else {
            cp_wait0();
        }
        __syncthreads();
        int buf = t & 1;
#pragma unroll
        for (int k = 0; k < 16; k++) {
            float4 a0 = *reinterpret_cast<const float4*>(&sX[buf][k][m0]);
            float4 a1 = *reinterpret_cast<const float4*>(&sX[buf][k][m0 + 4]);
            float4 b  = *reinterpret_cast<const float4*>(&sW[buf][k][o0]);
            float av[8] = {a0.x, a0.y, a0.z, a0.w, a1.x, a1.y, a1.z, a1.w};
            float bv[4] = {b.x, b.y, b.z, b.w};
#pragma unroll
            for (int i = 0; i < 8; i++)
#pragma unroll
                for (int j = 0; j < 4; j++) acc[i][j] += av[i] * bv[j];
        }
        __syncthreads();
    }

#pragma unroll
    for (int i = 0; i < 8; i++) {
        int m = bm + m0 + i;
#pragma unroll
        for (int j = 0; j < 4; j++) {
            int o = bo + o0 + j;
            float v = acc[i][j] * jb.scale;
            if (jb.bias) v += jb.bias[o];
            if (jb.act == 1) v = v / (1.f + expf(-v));
            if (jb.out_mode == 0) {
                jb.C[(long long)m * jb.ldc + o] = v;
            } else {
                int cc = m / jb.nnodes;
                int n = m - cc * jb.nnodes;
                jb.C[(long long)n * 640 + 256 + o * 3 + cc] = v;
            }
        }
    }
}

__global__ void __launch_bounds__(256, 3)
gemm_multi(GemmJob j0, GemmJob j1, GemmJob j2) {
    int b = blockIdx.x;
    GemmJob jb = (b >= j2.off) ? j2 : (b >= j1.off) ? j1 : j0;
    int local = b - jb.off;
    gemm_body(jb, local % jb.gx, local / jb.gx);
}

// ---------------- helpers ----------------
__device__ __forceinline__ void red4(float* addr, float a, float b, float c, float d) {
    asm volatile("red.global.add.v4.f32 [%0], {%1,%2,%3,%4};"
                 :: "l"(addr), "f"(a), "f"(b), "f"(c), "f"(d) : "memory");
}
__device__ __forceinline__ float ssp_f(float x) {
    const float ln2 = 0.69314718055994531f;
    return fmaxf(x, 0.f) + log1pf(expf(-fabsf(x))) - ln2;
}

// ---------------- fused edge kernel (round-9 champion, inv32 folded) ----------------
#define ETILE 96
#define ETHREADS 768
#define OFF_WF1 0
#define OFF_WF2 (OFF_WF1 + 1024)
#define OFF_WC  (OFF_WF2 + 12288)
#define OFF_WL2 (OFF_WC + 2048)
#define OFF_EA  (OFF_WL2 + 12288)
#define OFF_NL  (OFF_EA + 96*33)
#define OFF_IP  (OFF_NL + 96*33)
#define OFF_EAT (OFF_IP + 96*65)
#define OFF_IPT (OFF_EAT + 32*96)
#define OFF_HF  (OFF_IPT + 64*96)
#define OFF_HL  (OFF_HF + 32*96)
#define OFF_SH  (OFF_HL + 32*96)
#define OFF_END (OFF_SH + 384)
#define EDGE_SMEM_BYTES (OFF_END*4 + 192*4)

__global__ void __launch_bounds__(ETHREADS, 1)
edge_kernel(const float* __restrict__ edge_attr,
            const float* __restrict__ edge_sh,
            const float* __restrict__ Wf1, const float* __restrict__ Wf2,
            const float* __restrict__ Wl1, const float* __restrict__ Wl2,
            int E, int N) {
    extern __shared__ float sm[];
    float* sWf1 = sm + OFF_WF1;
    float* sWf2 = sm + OFF_WF2;
    float* sWc  = sm + OFF_WC;
    float* sWl2 = sm + OFF_WL2;
    float* sea  = sm + OFF_EA;
    float* snl  = sm + OFF_NL;
    float* sip  = sm + OFF_IP;
    float* seaT = sm + OFF_EAT;
    float* sipT = sm + OFF_IPT;
    float* shfT = sm + OFF_HF;
    float* shlT = sm + OFF_HL;
    float* ssh  = sm + OFF_SH;
    int*   sidx = (int*)(sm + OFF_END);

    int tid = threadIdx.x;
    for (int i = tid; i < 1024;  i += ETHREADS) sWf1[i] = Wf1[i];
    for (int i = tid; i < 12288; i += ETHREADS) sWf2[i] = Wf2[i];
    for (int i = tid; i < 2048;  i += ETHREADS) sWc[i]  = Wl1[256 * 32 + i];
    for (int i = tid; i < 12288; i += ETHREADS) sWl2[i] = Wl2[i];

    const float c0 = 0.5f, c1 = 0.86602540378443865f;
    const float inv3 = 1.f / 3.f;
    const float invs32 = 0.17677669529663687f;
    const float invs320 = 0.05590169943749474f;
    const float invs3 = 0.57735026918962576f;

    int warp = tid >> 5, lane = tid & 31;
    int eb = warp * 4;

    int ntiles = (E + ETILE - 1) / ETILE;
    for (int tile = blockIdx.x; tile < ntiles; tile += gridDim.x) {
        int e0 = tile * ETILE;
        int cnt = min(ETILE, E - e0);
        __syncthreads();

        if (tid < ETILE) {
            int valid = tid < cnt;
            sidx[tid]         = valid ? g_ei[e0 + tid]     : 0;
            sidx[ETILE + tid] = valid ? g_ei[E + e0 + tid] : 0;
        }
        for (int i = tid; i < ETILE * 4; i += ETHREADS) {
            int t = i >> 2, q = i & 3;
            ssh[i] = (t < cnt) ? edge_sh[(size_t)(e0 + t) * 4 + q] : 0.f;
        }
        for (int i = tid; i < ETILE * 32; i += ETHREADS) {
            int t = i >> 5, q = i & 31;
            sea[t * 33 + q] = (t < cnt) ? edge_attr[(size_t)(e0 + t) * 32 + q] : 0.f;
        }
        __syncthreads();

        for (int i = tid; i < ETILE * 64; i += ETHREADS) {
            int t = i >> 6, u = i & 63;
            int d = sidx[t], s = sidx[ETILE + t];
            float acc = 0.f;
#pragma unroll
            for (int c = 0; c < 3; c++)
                acc += g_pre_v[((size_t)c * N + d) * 64 + u] *
                       g_pre_v[((size_t)c * N + s) * 64 + u];
            sip[t * 65 + u] = acc * inv3;
        }
        for (int i = tid; i < ETILE * 32; i += ETHREADS) {
            int t = i >> 5, j = i & 31;
            snl[t * 33 + j] = g_nl1[(size_t)sidx[t] * 32 + j];
        }
        __syncthreads();

        for (int i = tid; i < 32 * ETILE; i += ETHREADS) {
            int t = i % ETILE, q = i / ETILE;
            seaT[q * ETILE + t] = sea[t * 33 + q];
        }
        for (int i = tid; i < 64 * ETILE; i += ETHREADS) {
            int t = i % ETILE, u = i / ETILE;
            sipT[u * ETILE + t] = sip[t * 65 + u];
        }
        __syncthreads();

        if (warp < 6) {
            int idx = tid;
            int t0 = (idx % 24) * 4, j0 = (idx / 24) * 4;
            float acc[4][4];
#pragma unroll
            for (int a = 0; a < 4; a++)
#pragma unroll
                for (int b = 0; b < 4; b++) acc[a][b] = 0.f;
#pragma unroll 4
            for (int q = 0; q < 32; q++) {
                float4 hv = *reinterpret_cast<const float4*>(&seaT[q * ETILE + t0]);
                float4 wv = *reinterpret_cast<const float4*>(&sWf1[q * 32 + j0]);
                float h[4] = {hv.x, hv.y, hv.z, hv.w};
                float w[4] = {wv.x, wv.y, wv.z, wv.w};
#pragma unroll
                for (int a = 0; a < 4; a++)
#pragma unroll
                    for (int b = 0; b < 4; b++) acc[a][b] += h[a] * w[b];
            }
#pragma unroll
            for (int b = 0; b < 4; b++) {
                float4 o;
                o.x = ssp_f(acc[0][b] * invs32) * invs32;
                o.y = ssp_f(acc[1][b] * invs32) * invs32;
                o.z = ssp_f(acc[2][b] * invs32) * invs32;
                o.w = ssp_f(acc[3][b] * invs32) * invs32;
                *reinterpret_cast<float4*>(&shfT[(j0 + b) * ETILE + t0]) = o;
            }
        } else if (warp < 18) {
            int idx = tid - 192;
            int t0 = (idx % 48) * 2, j0 = (idx / 48) * 4;
            float acc[2][4];
#pragma unroll
            for (int a = 0; a < 2; a++)
#pragma unroll
                for (int b = 0; b < 4; b++) acc[a][b] = snl[(t0 + a) * 33 + j0 + b];
#pragma unroll 4
            for (int u = 0; u < 64; u++) {
                float2 hv = *reinterpret_cast<const float2*>(&sipT[u * ETILE + t0]);
                float4 wv = *reinterpret_cast<const float4*>(&sWc[u * 32 + j0]);
                float h[2] = {hv.x, hv.y};
                float w[4] = {wv.x, wv.y, wv.z, wv.w};
#pragma unroll
                for (int a = 0; a < 2; a++)
#pragma unroll
                    for (int b = 0; b < 4; b++) acc[a][b] += h[a] * w[b];
            }
#pragma unroll
            for (int b = 0; b < 4; b++) {
                float2 o;
                o.x = ssp_f(acc[0][b] * invs320) * invs32;
                o.y = ssp_f(acc[1][b] * invs320) * invs32;
                *reinterpret_cast<float2*>(&shlT[(j0 + b) * ETILE + t0]) = o;
            }
        }
        __syncthreads();

#pragma unroll 1
        for (int ob = 0; ob < 3; ob++) {
            int o0 = ob * 128 + lane * 4;
            float wf[4][4], wl[4][4];
#pragma unroll
            for (int a = 0; a < 4; a++)
#pragma unroll
                for (int b = 0; b < 4; b++) { wf[a][b] = 0.f; wl[a][b] = 0.f; }

#pragma unroll 2
            for (int j = 0; j < 32; j++) {
                float4 hf = *reinterpret_cast<const float4*>(&shfT[j * ETILE + eb]);
                float4 hl = *reinterpret_cast<const float4*>(&shlT[j * ETILE + eb]);
                float4 af = *reinterpret_cast<const float4*>(&sWf2[j * 384 + o0]);
                float4 al = *reinterpret_cast<const float4*>(&sWl2[j * 384 + o0]);
                float hfv[4] = {hf.x, hf.y, hf.z, hf.w};
                float hlv[4] = {hl.x, hl.y, hl.z, hl.w};
                float afv[4] = {af.x, af.y, af.z, af.w};
                float alv[4] = {al.x, al.y, al.z, al.w};
#pragma unroll
                for (int a = 0; a < 4; a++)
#pragma unroll
                    for (int b = 0; b < 4; b++) {
                        wf[a][b] += hfv[a] * afv[b];
                        wl[a][b] += hlv[a] * alv[b];
                    }
            }

#pragma unroll
            for (int a = 0; a < 4; a++) {
                int t = eb + a;
                if (t >= cnt) continue;
                int d = sidx[t], s = sidx[ETILE + t];
                float sh0 = ssh[t * 4 + 0];
                float w0 = wf[a][0] * wl[a][0];
                float w1 = wf[a][1] * wl[a][1];
                float w2 = wf[a][2] * wl[a][2];
                float w3 = wf[a][3] * wl[a][3];
                if (o0 < 128) {
                    float4 hs = *reinterpret_cast<const float4*>(&g_xs3[(size_t)s * 128 + o0]);
                    float k = c0 * sh0;
                    red4(&g_ns[(size_t)d * 192 + o0],
                         k * w0 * hs.x, k * w1 * hs.y, k * w2 * hs.z, k * w3 * hs.w);
                } else if (o0 < 256) {
                    int u0 = o0 - 128;
                    float4 hs = *reinterpret_cast<const float4*>(&g_xs3[(size_t)s * 128 + u0]);
                    float b0 = c1 * w0 * hs.x, b1 = c1 * w1 * hs.y;
                    float b2 = c1 * w2 * hs.z, b3 = c1 * w3 * hs.w;
#pragma unroll
                    for (int c = 0; c < 3; c++) {
                        float shc = ssh[t * 4 + 1 + c];
                        red4(&g_nv[((size_t)c * N + d) * 192 + u0],
                             b0 * shc, b1 * shc, b2 * shc, b3 * shc);
                    }
                } else if (o0 < 320) {
                    int u0 = o0 - 256;
                    float b0 = c1 * w0 * sh0, b1 = c1 * w1 * sh0;
                    float b2 = c1 * w2 * sh0, b3 = c1 * w3 * sh0;
#pragma unroll
                    for (int c = 0; c < 3; c++) {
                        float4 hv = *reinterpret_cast<const float4*>(
                            &g_xv3[((size_t)c * N + s) * 64 + u0]);
                        red4(&g_nv[((size_t)c * N + d) * 192 + 128 + u0],
                             b0 * hv.x, b1 * hv.y, b2 * hv.z, b3 * hv.w);
                    }
                } else {
                    int u0 = o0 - 320;
                    float4 hx = *reinterpret_cast<const float4*>(&g_xv3[((size_t)0 * N + s) * 64 + u0]);
                    float4 hy = *reinterpret_cast<const float4*>(&g_xv3[((size_t)1 * N + s) * 64 + u0]);
                    float4 hz = *reinterpret_cast<const float4*>(&g_xv3[((size_t)2 * N + s) * 64 + u0]);
                    float sh1 = ssh[t * 4 + 1], sh2v = ssh[t * 4 + 2], sh3 = ssh[t * 4 + 3];
                    float k = c0 * invs3;
                    red4(&g_ns[(size_t)d * 192 + 128 + u0],
                         k * w0 * (hx.x * sh1 + hy.x * sh2v + hz.x * sh3),
                         k * w1 * (hx.y * sh1 + hy.y * sh2v + hz.y * sh3),
                         k * w2 * (hx.z * sh1 + hy.z * sh2v + hz.z * sh3),
                         k * w3 * (hx.w * sh1 + hy.w * sh2v + hz.w * sh3));
                }
            }
        }
    }
}

// ---------------- launch ----------------
static GemmJob mkjob(const float* X, int ldx, const float* W, int ldw,
                     float* C, int ldc, int M, int K, int O,
                     float scale, const float* bias, int act,
                     int out_mode, int nnodes, int off) {
    GemmJob j;
    j.X = X; j.W = W; j.C = C; j.bias = bias;
    j.ldx = ldx; j.ldw = ldw; j.ldc = ldc;
    j.K = K; j.scale = scale; j.act = act;
    j.out_mode = out_mode; j.nnodes = nnodes;
    j.gx = O / 64; j.gy = M / 128; j.off = off;
    return j;
}

extern "C" void kernel_launch(void* const* d_in, const int* in_sizes, int n_in,
                              void* d_out, int out_size) {
    const float* x      = (const float*)d_in[0];
    const int*   ei_raw = (const int*)d_in[1];
    const float* ea     = (const float*)d_in[2];
    const float* esh    = (const float*)d_in[3];
    const float* Wpre_s = (const float*)d_in[4];
    const float* bpre_s = (const float*)d_in[5];
    const float* Wpre_v = (const float*)d_in[6];
    const float* Wg1    = (const float*)d_in[7];
    const float* bg1    = (const float*)d_in[8];
    const float* Wg2    = (const float*)d_in[9];
    const float* bg2    = (const float*)d_in[10];
    const float* Wn_s   = (const float*)d_in[11];
    const float* bn_s   = (const float*)d_in[12];
    const float* Wn_v   = (const float*)d_in[13];
    const float* Wf1    = (const float*)d_in[14];
    const float* Wf2    = (const float*)d_in[15];
    const float* Wl1    = (const float*)d_in[16];
    const float* Wl2    = (const float*)d_in[17];
    const float* Wo_s   = (const float*)d_in[18];
    const float* bo_s   = (const float*)d_in[19];
    const float* Wo_v   = (const float*)d_in[20];

    int N = in_sizes[0] / 320;
    int E = in_sizes[1] / 2;
    float* out = (float*)d_out;

    float *p_xvT, *p_f0, *p_pre_s, *p_pre_v, *p_h1, *p_g, *p_xv2T, *p_xs3, *p_ns, *p_nv, *p_xv3;
    cudaGetSymbolAddress((void**)&p_xvT,  g_xvT);
    cudaGetSymbolAddress((void**)&p_f0,   g_f0);
    cudaGetSymbolAddress((void**)&p_pre_s,g_pre_s);
    cudaGetSymbolAddress((void**)&p_pre_v,g_pre_v);
    cudaGetSymbolAddress((void**)&p_h1,   g_h1);
    cudaGetSymbolAddress((void**)&p_g,    g_g);
    cudaGetSymbolAddress((void**)&p_xv2T, g_xv2T);
    cudaGetSymbolAddress((void**)&p_xs3,  g_xs3);
    cudaGetSymbolAddress((void**)&p_ns,   g_ns);
    cudaGetSymbolAddress((void**)&p_nv,   g_nv);
    cudaGetSymbolAddress((void**)&p_xv3,  g_xv3);

    const float s128 = 0.08838834764831845f;
    const float s64  = 0.125f;
    const float s192 = 0.07216878364870323f;

    // fused setup: convert + prep + wsum + zero (all off the GEMM critical path)
    setup_kernel<<<2048, 256>>>(ei_raw, x, Wl1, N, E);

    // Phase A: pre_s | pre_v | h1
    {
        GemmJob jA = mkjob(x, 320, Wpre_s, 128, p_pre_s, 128, N, 128, 128, s128, bpre_s, 0, 0, 0, 0);
        int c0 = jA.gx * jA.gy;
        GemmJob jB = mkjob(p_xvT, 64, Wpre_v, 64, p_pre_v, 64, 3 * N, 64, 64, s64, nullptr, 0, 0, 0, c0);
        int c1 = c0 + jB.gx * jB.gy;
        GemmJob jC = mkjob(p_f0, 192, Wg1, 192, p_h1, 192, N, 192, 192, 1.f, bg1, 1, 0, 0, c1);
        int total = c1 + jC.gx * jC.gy;
        gemm_multi<<<total, 256>>>(jA, jB, jC);
    }
    // g = h1 @ Wg2 + bg2
    {
        GemmJob jA = mkjob(p_h1, 192, Wg2, 192, p_g, 192, N, 192, 192, 1.f, bg2, 0, 0, 0, 0);
        int total = jA.gx * jA.gy;
        GemmJob jX = jA; jX.off = total;
        gemm_multi<<<total, 256>>>(jA, jX, jX);
    }

    gate_kernel<<<2048, 256>>>(N);
    nl1_kernel<<<(N + 7) / 8, 256>>>(N);

    // Phase B: xs3 (K=128) | xv3
    {
        GemmJob jA = mkjob(p_g, 192, Wn_s, 128, p_xs3, 128, N, 128, 128, s128, bn_s, 0, 0, 0, 0);
        int c0 = jA.gx * jA.gy;
        GemmJob jB = mkjob(p_xv2T, 64, Wn_v, 64, p_xv3, 64, 3 * N, 64, 64, s64, nullptr, 0, 0, 0, c0);
        int total = c0 + jB.gx * jB.gy;
        GemmJob jX = jB; jX.off = total;
        gemm_multi<<<total, 256>>>(jA, jB, jX);
    }

    cudaFuncSetAttribute(edge_kernel, cudaFuncAttributeMaxDynamicSharedMemorySize,
                         EDGE_SMEM_BYTES);
    edge_kernel<<<148, ETHREADS, EDGE_SMEM_BYTES>>>(ea, esh, Wf1, Wf2, Wl1, Wl2, E, N);

    // Phase C: outs | outv
    {
        GemmJob jA = mkjob(p_ns, 192, Wo_s, 256, out, 640, N, 192, 256, s192, bo_s, 0, 0, 0, 0);
        int c0 = jA.gx * jA.gy;
        GemmJob jB = mkjob(p_nv, 192, Wo_v, 128, out, 0, 3 * N, 192, 128, s192, nullptr, 0, 1, N, c0);
        int total = c0 + jB.gx * jB.gy;
        GemmJob jX = jB; jX.off = total;
        gemm_multi<<<total, 256>>>(jA, jB, jX);
    }
}

// round 17
// speedup vs baseline: 1.0029x; 1.0029x over previous
#include <cuda_runtime.h>
#include <math.h>

#define NMAX 16000
#define EMAX 256000

// ---------------- static device scratch ----------------
__device__ float g_xvT [3*NMAX*64];
__device__ float g_f0  [NMAX*192];
__device__ float g_pre_s[NMAX*128];
__device__ float g_pre_v[3*NMAX*64];
__device__ float g_h1  [NMAX*192];
__device__ float g_g   [NMAX*192];
__device__ float g_xv2T[3*NMAX*64];
__device__ float g_xs3 [NMAX*128];
__device__ float g_xv3 [3*NMAX*64];
__device__ float g_ns  [NMAX*192];
__device__ float g_nv  [3*NMAX*192];
__device__ float g_nl1 [NMAX*32];
__device__ float g_Wl1c[128*32];
__device__ int   g_ei  [2*EMAX];

// ---------------- edge-index convert with inline dtype detection ----------------
__global__ void convert_kernel(const int* __restrict__ ei_raw, int total) {
    __shared__ int s_is64;
    if (threadIdx.x == 0) {
        int nz = 0;
        for (int i = 1; i < 256; i += 2) nz += (ei_raw[i] != 0);
        s_is64 = (nz == 0) ? 1 : 0;
    }
    __syncthreads();
    int is64 = s_is64;
    for (int idx = blockIdx.x * blockDim.x + threadIdx.x; idx < total;
         idx += gridDim.x * blockDim.x)
        g_ei[idx] = is64 ? ei_raw[2 * idx] : ei_raw[idx];
}

// ---------------- prep ----------------
__global__ void prep_kernel(const float* __restrict__ x, int N) {
    int total = N * 192;
    for (int idx = blockIdx.x * blockDim.x + threadIdx.x; idx < total;
         idx += gridDim.x * blockDim.x) {
        int n = idx / 192, i = idx - n * 192;
        if (i < 128) {
            g_f0[n * 192 + i] = x[n * 320 + i];
        } else {
            int u = i - 128;
            float a = x[n * 320 + 128 + 3 * u + 0];
            float b = x[n * 320 + 128 + 3 * u + 1];
            float c = x[n * 320 + 128 + 3 * u + 2];
            g_xvT[(0 * N + n) * 64 + u] = a;
            g_xvT[(1 * N + n) * 64 + u] = b;
            g_xvT[(2 * N + n) * 64 + u] = c;
            g_f0[n * 192 + i] = sqrtf(a * a + b * b + c * c + 1e-12f);
        }
    }
}

__global__ void zero_kernel(int N) {
    int t1 = N * 192, t2 = 3 * N * 192, total = t1 + t2;
    for (int idx = blockIdx.x * blockDim.x + threadIdx.x; idx < total;
         idx += gridDim.x * blockDim.x) {
        if (idx < t1) g_ns[idx] = 0.f;
        else          g_nv[idx - t1] = 0.f;
    }
}

__global__ void wsum_kernel(const float* __restrict__ Wl1) {
    int idx = blockIdx.x * blockDim.x + threadIdx.x;
    if (idx < 128 * 32) g_Wl1c[idx] = Wl1[idx] + Wl1[128 * 32 + idx];
}

// ---------------- cp.async helpers ----------------
__device__ __forceinline__ void cp_async4(unsigned saddr, const float* gptr) {
    asm volatile("cp.async.ca.shared.global [%0], [%1], 4;" :: "r"(saddr), "l"(gptr));
}
__device__ __forceinline__ void cp_commit() {
    asm volatile("cp.async.commit_group;" ::: "memory");
}
__device__ __forceinline__ void cp_wait1() {
    asm volatile("cp.async.wait_group 1;" ::: "memory");
}
__device__ __forceinline__ void cp_wait0() {
    asm volatile("cp.async.wait_group 0;" ::: "memory");
}

// ---------------- multi-job SGEMM, flat 1D grid, cp.async double-buffered ----------------
// out_mode 0: C[m*ldc + o]
// out_mode 1: vector interleave into d_out
// out_mode 2: g job with fused gate: o<128 -> C; o>=128 -> xv2T = xvT * v
struct GemmJob {
    const float* X; const float* W; float* C; const float* bias;
    int ldx, ldw, ldc;
    int K;
    float scale;
    int act, out_mode, nnodes;
    int gx, gy, off;
};

__device__ __forceinline__ void gemm_body(const GemmJob& jb, int bx, int by) {
    __shared__ __align__(16) float sX[2][16][132];
    __shared__ __align__(16) float sW[2][16][68];
    int bm = by * 128, bo = bx * 64;
    int tid = threadIdx.x;
    int tr = tid >> 4, tc = tid & 15;
    int m0 = tr * 8, o0 = tc * 4;

    float acc[8][4];
#pragma unroll
    for (int i = 0; i < 8; i++)
#pragma unroll
        for (int j = 0; j < 4; j++) acc[i][j] = 0.f;

    unsigned sxa[8], swa[4];
    int gxo[8], gwo[4];
#pragma unroll
    for (int l = 0; l < 8; l++) {
        int i = tid + l * 256;
        int r = i >> 4, c = i & 15;
        sxa[l] = (unsigned)__cvta_generic_to_shared(&sX[0][c][r]);
        gxo[l] = (bm + r) * jb.ldx + c;
    }
#pragma unroll
    for (int l = 0; l < 4; l++) {
        int i = tid + l * 256;
        int r = i >> 6, c = i & 63;
        swa[l] = (unsigned)__cvta_generic_to_shared(&sW[0][r][c]);
        gwo[l] = r * jb.ldw + bo + c;
    }
    const unsigned SXB = 16 * 132 * 4;
    const unsigned SWB = 16 * 68 * 4;

    int ntiles = jb.K >> 4;
#pragma unroll
    for (int l = 0; l < 8; l++) cp_async4(sxa[l], jb.X + gxo[l]);
#pragma unroll
    for (int l = 0; l < 4; l++) cp_async4(swa[l], jb.W + gwo[l]);
    cp_commit();

    for (int t = 0; t < ntiles; t++) {
        if (t + 1 < ntiles) {
            int k0 = (t + 1) << 4;
            unsigned bofX = ((t + 1) & 1) ? SXB : 0u;
            unsigned bofW = ((t + 1) & 1) ? SWB : 0u;
            int wstep = k0 * jb.ldw;
#pragma unroll
            for (int l = 0; l < 8; l++)
                cp_async4(sxa[l] + bofX, jb.X + gxo[l] + k0);
#pragma unroll
            for (int l = 0; l < 4; l++)
                cp_async4(swa[l] + bofW, jb.W + gwo[l] + wstep);
            cp_commit();
            cp_wait1();
        } else {
            cp_wait0();
        }
        __syncthreads();
        int buf = t & 1;
#pragma unroll
        for (int k = 0; k < 16; k++) {
            float4 a0 = *reinterpret_cast<const float4*>(&sX[buf][k][m0]);
            float4 a1 = *reinterpret_cast<const float4*>(&sX[buf][k][m0 + 4]);
            float4 b  = *reinterpret_cast<const float4*>(&sW[buf][k][o0]);
            float av[8] = {a0.x, a0.y, a0.z, a0.w, a1.x, a1.y, a1.z, a1.w};
            float bv[4] = {b.x, b.y, b.z, b.w};
#pragma unroll
            for (int i = 0; i < 8; i++)
#pragma unroll
                for (int j = 0; j < 4; j++) acc[i][j] += av[i] * bv[j];
        }
        __syncthreads();
    }

    int N = jb.nnodes;
#pragma unroll
    for (int i = 0; i < 8; i++) {
        int m = bm + m0 + i;
#pragma unroll
        for (int j = 0; j < 4; j++) {
            int o = bo + o0 + j;
            float v = acc[i][j] * jb.scale;
            if (jb.bias) v += jb.bias[o];
            if (jb.act == 1) v = v / (1.f + expf(-v));
            if (jb.out_mode == 0) {
                jb.C[(long long)m * jb.ldc + o] = v;
            } else if (jb.out_mode == 2) {
                if (o < 128) {
                    jb.C[(long long)m * jb.ldc + o] = v;
                } else {
                    int u = o - 128;
#pragma unroll
                    for (int c = 0; c < 3; c++) {
                        size_t ix = ((size_t)c * N + m) * 64 + u;
                        g_xv2T[ix] = g_xvT[ix] * v;
                    }
                }
            } else {
                int cc = m / N;
                int n = m - cc * N;
                jb.C[(long long)n * 640 + 256 + o * 3 + cc] = v;
            }
        }
    }
}

__global__ void __launch_bounds__(256, 3)
gemm_multi(GemmJob j0, GemmJob j1, GemmJob j2) {
    int b = blockIdx.x;
    GemmJob jb = (b >= j2.off) ? j2 : (b >= j1.off) ? j1 : j0;
    int local = b - jb.off;
    gemm_body(jb, local % jb.gx, local / jb.gx);
}

// phase B + nl1 combined: blocks [0, nl1_off) = gemm jobs; rest = nl1
__global__ void __launch_bounds__(256, 3)
gemm_nl1_multi(GemmJob j0, GemmJob j1, int nl1_off, int N) {
    int b = blockIdx.x;
    if (b < nl1_off) {
        GemmJob jb = (b >= j1.off) ? j1 : j0;
        int local = b - jb.off;
        gemm_body(jb, local % jb.gx, local / jb.gx);
    } else {
        __shared__ float sWn[128 * 32];
        int tid = threadIdx.x;
        for (int i = tid; i < 128 * 32; i += 256) sWn[i] = g_Wl1c[i];
        __syncthreads();
        int j = tid & 31;
        int n = (b - nl1_off) * 8 + (tid >> 5);
        if (n >= N) return;
        const float* row = &g_pre_s[(size_t)n * 128];
        float acc = 0.f;
#pragma unroll 8
        for (int q = 0; q < 128; q++) acc += row[q] * sWn[q * 32 + j];
        g_nl1[(size_t)n * 32 + j] = acc;
    }
}

// ---------------- helpers ----------------
__device__ __forceinline__ void red4(float* addr, float a, float b, float c, float d) {
    asm volatile("red.global.add.v4.f32 [%0], {%1,%2,%3,%4};"
                 :: "l"(addr), "f"(a), "f"(b), "f"(c), "f"(d) : "memory");
}
__device__ __forceinline__ float ssp_f(float x) {
    const float ln2 = 0.69314718055994531f;
    return fmaxf(x, 0.f) + log1pf(expf(-fabsf(x))) - ln2;
}

// ---------------- fused edge kernel (champion, inv32 folded) ----------------
#define ETILE 96
#define ETHREADS 768
#define OFF_WF1 0
#define OFF_WF2 (OFF_WF1 + 1024)
#define OFF_WC  (OFF_WF2 + 12288)
#define OFF_WL2 (OFF_WC + 2048)
#define OFF_EA  (OFF_WL2 + 12288)
#define OFF_NL  (OFF_EA + 96*33)
#define OFF_IP  (OFF_NL + 96*33)
#define OFF_EAT (OFF_IP + 96*65)
#define OFF_IPT (OFF_EAT + 32*96)
#define OFF_HF  (OFF_IPT + 64*96)
#define OFF_HL  (OFF_HF + 32*96)
#define OFF_SH  (OFF_HL + 32*96)
#define OFF_END (OFF_SH + 384)
#define EDGE_SMEM_BYTES (OFF_END*4 + 192*4)

__global__ void __launch_bounds__(ETHREADS, 1)
edge_kernel(const float* __restrict__ edge_attr,
            const float* __restrict__ edge_sh,
            const float* __restrict__ Wf1, const float* __restrict__ Wf2,
            const float* __restrict__ Wl1, const float* __restrict__ Wl2,
            int E, int N) {
    extern __shared__ float sm[];
    float* sWf1 = sm + OFF_WF1;
    float* sWf2 = sm + OFF_WF2;
    float* sWc  = sm + OFF_WC;
    float* sWl2 = sm + OFF_WL2;
    float* sea  = sm + OFF_EA;
    float* snl  = sm + OFF_NL;
    float* sip  = sm + OFF_IP;
    float* seaT = sm + OFF_EAT;
    float* sipT = sm + OFF_IPT;
    float* shfT = sm + OFF_HF;
    float* shlT = sm + OFF_HL;
    float* ssh  = sm + OFF_SH;
    int*   sidx = (int*)(sm + OFF_END);

    int tid = threadIdx.x;
    for (int i = tid; i < 1024;  i += ETHREADS) sWf1[i] = Wf1[i];
    for (int i = tid; i < 12288; i += ETHREADS) sWf2[i] = Wf2[i];
    for (int i = tid; i < 2048;  i += ETHREADS) sWc[i]  = Wl1[256 * 32 + i];
    for (int i = tid; i < 12288; i += ETHREADS) sWl2[i] = Wl2[i];

    const float c0 = 0.5f, c1 = 0.86602540378443865f;
    const float inv3 = 1.f / 3.f;
    const float invs32 = 0.17677669529663687f;
    const float invs320 = 0.05590169943749474f;
    const float invs3 = 0.57735026918962576f;

    int warp = tid >> 5, lane = tid & 31;
    int eb = warp * 4;

    int ntiles = (E + ETILE - 1) / ETILE;
    for (int tile = blockIdx.x; tile < ntiles; tile += gridDim.x) {
        int e0 = tile * ETILE;
        int cnt = min(ETILE, E - e0);
        __syncthreads();

        if (tid < ETILE) {
            int valid = tid < cnt;
            sidx[tid]         = valid ? g_ei[e0 + tid]     : 0;
            sidx[ETILE + tid] = valid ? g_ei[E + e0 + tid] : 0;
        }
        for (int i = tid; i < ETILE * 4; i += ETHREADS) {
            int t = i >> 2, q = i & 3;
            ssh[i] = (t < cnt) ? edge_sh[(size_t)(e0 + t) * 4 + q] : 0.f;
        }
        for (int i = tid; i < ETILE * 32; i += ETHREADS) {
            int t = i >> 5, q = i & 31;
            sea[t * 33 + q] = (t < cnt) ? edge_attr[(size_t)(e0 + t) * 32 + q] : 0.f;
        }
        __syncthreads();

        for (int i = tid; i < ETILE * 64; i += ETHREADS) {
            int t = i >> 6, u = i & 63;
            int d = sidx[t], s = sidx[ETILE + t];
            float acc = 0.f;
#pragma unroll
            for (int c = 0; c < 3; c++)
                acc += g_pre_v[((size_t)c * N + d) * 64 + u] *
                       g_pre_v[((size_t)c * N + s) * 64 + u];
            sip[t * 65 + u] = acc * inv3;
        }
        for (int i = tid; i < ETILE * 32; i += ETHREADS) {
            int t = i >> 5, j = i & 31;
            snl[t * 33 + j] = g_nl1[(size_t)sidx[t] * 32 + j];
        }
        __syncthreads();

        for (int i = tid; i < 32 * ETILE; i += ETHREADS) {
            int t = i % ETILE, q = i / ETILE;
            seaT[q * ETILE + t] = sea[t * 33 + q];
        }
        for (int i = tid; i < 64 * ETILE; i += ETHREADS) {
            int t = i % ETILE, u = i / ETILE;
            sipT[u * ETILE + t] = sip[t * 65 + u];
        }
        __syncthreads();

        if (warp < 6) {
            int idx = tid;
            int t0 = (idx % 24) * 4, j0 = (idx / 24) * 4;
            float acc[4][4];
#pragma unroll
            for (int a = 0; a < 4; a++)
#pragma unroll
                for (int b = 0; b < 4; b++) acc[a][b] = 0.f;
#pragma unroll 4
            for (int q = 0; q < 32; q++) {
                float4 hv = *reinterpret_cast<const float4*>(&seaT[q * ETILE + t0]);
                float4 wv = *reinterpret_cast<const float4*>(&sWf1[q * 32 + j0]);
                float h[4] = {hv.x, hv.y, hv.z, hv.w};
                float w[4] = {wv.x, wv.y, wv.z, wv.w};
#pragma unroll
                for (int a = 0; a < 4; a++)
#pragma unroll
                    for (int b = 0; b < 4; b++) acc[a][b] += h[a] * w[b];
            }
#pragma unroll
            for (int b = 0; b < 4; b++) {
                float4 o;
                o.x = ssp_f(acc[0][b] * invs32) * invs32;
                o.y = ssp_f(acc[1][b] * invs32) * invs32;
                o.z = ssp_f(acc[2][b] * invs32) * invs32;
                o.w = ssp_f(acc[3][b] * invs32) * invs32;
                *reinterpret_cast<float4*>(&shfT[(j0 + b) * ETILE + t0]) = o;
            }
        } else if (warp < 18) {
            int idx = tid - 192;
            int t0 = (idx % 48) * 2, j0 = (idx / 48) * 4;
            float acc[2][4];
#pragma unroll
            for (int a = 0; a < 2; a++)
#pragma unroll
                for (int b = 0; b < 4; b++) acc[a][b] = snl[(t0 + a) * 33 + j0 + b];
#pragma unroll 4
            for (int u = 0; u < 64; u++) {
                float2 hv = *reinterpret_cast<const float2*>(&sipT[u * ETILE + t0]);
                float4 wv = *reinterpret_cast<const float4*>(&sWc[u * 32 + j0]);
                float h[2] = {hv.x, hv.y};
                float w[4] = {wv.x, wv.y, wv.z, wv.w};
#pragma unroll
                for (int a = 0; a < 2; a++)
#pragma unroll
                    for (int b = 0; b < 4; b++) acc[a][b] += h[a] * w[b];
            }
#pragma unroll
            for (int b = 0; b < 4; b++) {
                float2 o;
                o.x = ssp_f(acc[0][b] * invs320) * invs32;
                o.y = ssp_f(acc[1][b] * invs320) * invs32;
                *reinterpret_cast<float2*>(&shlT[(j0 + b) * ETILE + t0]) = o;
            }
        }
        __syncthreads();

#pragma unroll 1
        for (int ob = 0; ob < 3; ob++) {
            int o0 = ob * 128 + lane * 4;
            float wf[4][4], wl[4][4];
#pragma unroll
            for (int a = 0; a < 4; a++)
#pragma unroll
                for (int b = 0; b < 4; b++) { wf[a][b] = 0.f; wl[a][b] = 0.f; }

#pragma unroll 2
            for (int j = 0; j < 32; j++) {
                float4 hf = *reinterpret_cast<const float4*>(&shfT[j * ETILE + eb]);
                float4 hl = *reinterpret_cast<const float4*>(&shlT[j * ETILE + eb]);
                float4 af = *reinterpret_cast<const float4*>(&sWf2[j * 384 + o0]);
                float4 al = *reinterpret_cast<const float4*>(&sWl2[j * 384 + o0]);
                float hfv[4] = {hf.x, hf.y, hf.z, hf.w};
                float hlv[4] = {hl.x, hl.y, hl.z, hl.w};
                float afv[4] = {af.x, af.y, af.z, af.w};
                float alv[4] = {al.x, al.y, al.z, al.w};
#pragma unroll
                for (int a = 0; a < 4; a++)
#pragma unroll
                    for (int b = 0; b < 4; b++) {
                        wf[a][b] += hfv[a] * afv[b];
                        wl[a][b] += hlv[a] * alv[b];
                    }
            }

#pragma unroll
            for (int a = 0; a < 4; a++) {
                int t = eb + a;
                if (t >= cnt) continue;
                int d = sidx[t], s = sidx[ETILE + t];
                float sh0 = ssh[t * 4 + 0];
                float w0 = wf[a][0] * wl[a][0];
                float w1 = wf[a][1] * wl[a][1];
                float w2 = wf[a][2] * wl[a][2];
                float w3 = wf[a][3] * wl[a][3];
                if (o0 < 128) {
                    float4 hs = *reinterpret_cast<const float4*>(&g_xs3[(size_t)s * 128 + o0]);
                    float k = c0 * sh0;
                    red4(&g_ns[(size_t)d * 192 + o0],
                         k * w0 * hs.x, k * w1 * hs.y, k * w2 * hs.z, k * w3 * hs.w);
                } else if (o0 < 256) {
                    int u0 = o0 - 128;
                    float4 hs = *reinterpret_cast<const float4*>(&g_xs3[(size_t)s * 128 + u0]);
                    float b0 = c1 * w0 * hs.x, b1 = c1 * w1 * hs.y;
                    float b2 = c1 * w2 * hs.z, b3 = c1 * w3 * hs.w;
#pragma unroll
                    for (int c = 0; c < 3; c++) {
                        float shc = ssh[t * 4 + 1 + c];
                        red4(&g_nv[((size_t)c * N + d) * 192 + u0],
                             b0 * shc, b1 * shc, b2 * shc, b3 * shc);
                    }
                } else if (o0 < 320) {
                    int u0 = o0 - 256;
                    float b0 = c1 * w0 * sh0, b1 = c1 * w1 * sh0;
                    float b2 = c1 * w2 * sh0, b3 = c1 * w3 * sh0;
#pragma unroll
                    for (int c = 0; c < 3; c++) {
                        float4 hv = *reinterpret_cast<const float4*>(
                            &g_xv3[((size_t)c * N + s) * 64 + u0]);
                        red4(&g_nv[((size_t)c * N + d) * 192 + 128 + u0],
                             b0 * hv.x, b1 * hv.y, b2 * hv.z, b3 * hv.w);
                    }
                } else {
                    int u0 = o0 - 320;
                    float4 hx = *reinterpret_cast<const float4*>(&g_xv3[((size_t)0 * N + s) * 64 + u0]);
                    float4 hy = *reinterpret_cast<const float4*>(&g_xv3[((size_t)1 * N + s) * 64 + u0]);
                    float4 hz = *reinterpret_cast<const float4*>(&g_xv3[((size_t)2 * N + s) * 64 + u0]);
                    float sh1 = ssh[t * 4 + 1], sh2v = ssh[t * 4 + 2], sh3 = ssh[t * 4 + 3];
                    float k = c0 * invs3;
                    red4(&g_ns[(size_t)d * 192 + 128 + u0],
                         k * w0 * (hx.x * sh1 + hy.x * sh2v + hz.x * sh3),
                         k * w1 * (hx.y * sh1 + hy.y * sh2v + hz.y * sh3),
                         k * w2 * (hx.z * sh1 + hy.z * sh2v + hz.z * sh3),
                         k * w3 * (hx.w * sh1 + hy.w * sh2v + hz.w * sh3));
                }
            }
        }
    }
}

// ---------------- launch ----------------
static GemmJob mkjob(const float* X, int ldx, const float* W, int ldw,
                     float* C, int ldc, int M, int K, int O,
                     float scale, const float* bias, int act,
                     int out_mode, int nnodes, int off) {
    GemmJob j;
    j.X = X; j.W = W; j.C = C; j.bias = bias;
    j.ldx = ldx; j.ldw = ldw; j.ldc = ldc;
    j.K = K; j.scale = scale; j.act = act;
    j.out_mode = out_mode; j.nnodes = nnodes;
    j.gx = O / 64; j.gy = M / 128; j.off = off;
    return j;
}

extern "C" void kernel_launch(void* const* d_in, const int* in_sizes, int n_in,
                              void* d_out, int out_size) {
    const float* x      = (const float*)d_in[0];
    const int*   ei_raw = (const int*)d_in[1];
    const float* ea     = (const float*)d_in[2];
    const float* esh    = (const float*)d_in[3];
    const float* Wpre_s = (const float*)d_in[4];
    const float* bpre_s = (const float*)d_in[5];
    const float* Wpre_v = (const float*)d_in[6];
    const float* Wg1    = (const float*)d_in[7];
    const float* bg1    = (const float*)d_in[8];
    const float* Wg2    = (const float*)d_in[9];
    const float* bg2    = (const float*)d_in[10];
    const float* Wn_s   = (const float*)d_in[11];
    const float* bn_s   = (const float*)d_in[12];
    const float* Wn_v   = (const float*)d_in[13];
    const float* Wf1    = (const float*)d_in[14];
    const float* Wf2    = (const float*)d_in[15];
    const float* Wl1    = (const float*)d_in[16];
    const float* Wl2    = (const float*)d_in[17];
    const float* Wo_s   = (const float*)d_in[18];
    const float* bo_s   = (const float*)d_in[19];
    const float* Wo_v   = (const float*)d_in[20];

    int N = in_sizes[0] / 320;
    int E = in_sizes[1] / 2;
    float* out = (float*)d_out;

    float *p_xvT, *p_f0, *p_pre_s, *p_pre_v, *p_h1, *p_g, *p_xv2T, *p_xs3, *p_ns, *p_nv, *p_xv3;
    cudaGetSymbolAddress((void**)&p_xvT,  g_xvT);
    cudaGetSymbolAddress((void**)&p_f0,   g_f0);
    cudaGetSymbolAddress((void**)&p_pre_s,g_pre_s);
    cudaGetSymbolAddress((void**)&p_pre_v,g_pre_v);
    cudaGetSymbolAddress((void**)&p_h1,   g_h1);
    cudaGetSymbolAddress((void**)&p_g,    g_g);
    cudaGetSymbolAddress((void**)&p_xv2T, g_xv2T);
    cudaGetSymbolAddress((void**)&p_xs3,  g_xs3);
    cudaGetSymbolAddress((void**)&p_ns,   g_ns);
    cudaGetSymbolAddress((void**)&p_nv,   g_nv);
    cudaGetSymbolAddress((void**)&p_xv3,  g_xv3);

    const float s128 = 0.08838834764831845f;
    const float s64  = 0.125f;
    const float s192 = 0.07216878364870323f;

    convert_kernel<<<512, 256>>>(ei_raw, 2 * E);
    prep_kernel<<<2048, 256>>>(x, N);
    wsum_kernel<<<16, 256>>>(Wl1);

    // Phase A: pre_s | pre_v | h1
    {
        GemmJob jA = mkjob(x, 320, Wpre_s, 128, p_pre_s, 128, N, 128, 128, s128, bpre_s, 0, 0, N, 0);
        int c0 = jA.gx * jA.gy;
        GemmJob jB = mkjob(p_xvT, 64, Wpre_v, 64, p_pre_v, 64, 3 * N, 64, 64, s64, nullptr, 0, 0, N, c0);
        int c1 = c0 + jB.gx * jB.gy;
        GemmJob jC = mkjob(p_f0, 192, Wg1, 192, p_h1, 192, N, 192, 192, 1.f, bg1, 1, 0, N, c1);
        int total = c1 + jC.gx * jC.gy;
        gemm_multi<<<total, 256>>>(jA, jB, jC);
    }
    // g = h1 @ Wg2 + bg2, with fused gate (out_mode 2)
    {
        GemmJob jA = mkjob(p_h1, 192, Wg2, 192, p_g, 192, N, 192, 192, 1.f, bg2, 0, 2, N, 0);
        int total = jA.gx * jA.gy;
        GemmJob jX = jA; jX.off = total;
        gemm_multi<<<total, 256>>>(jA, jX, jX);
    }

    zero_kernel<<<2048, 256>>>(N);

    // Phase B: xs3 (K=128) | xv3 | nl1 (concurrent)
    {
        GemmJob jA = mkjob(p_g, 192, Wn_s, 128, p_xs3, 128, N, 128, 128, s128, bn_s, 0, 0, N, 0);
        int c0 = jA.gx * jA.gy;
        GemmJob jB = mkjob(p_xv2T, 64, Wn_v, 64, p_xv3, 64, 3 * N, 64, 64, s64, nullptr, 0, 0, N, c0);
        int gemm_total = c0 + jB.gx * jB.gy;
        int nl1_blocks = (N + 7) / 8;
        gemm_nl1_multi<<<gemm_total + nl1_blocks, 256>>>(jA, jB, gemm_total, N);
    }

    cudaFuncSetAttribute(edge_kernel, cudaFuncAttributeMaxDynamicSharedMemorySize,
                         EDGE_SMEM_BYTES);
    edge_kernel<<<148, ETHREADS, EDGE_SMEM_BYTES>>>(ea, esh, Wf1, Wf2, Wl1, Wl2, E, N);

    // Phase C: outs | outv
    {
        GemmJob jA = mkjob(p_ns, 192, Wo_s, 256, out, 640, N, 192, 256, s192, bo_s, 0, 0, N, 0);
        int c0 = jA.gx * jA.gy;
        GemmJob jB = mkjob(p_nv, 192, Wo_v, 128, out, 0, 3 * N, 192, 128, s192, nullptr, 0, 1, N, c0);
        int total = c0 + jB.gx * jB.gy;
        GemmJob jX = jB; jX.off = total;
        gemm_multi<<<total, 256>>>(jA, jB, jX);
    }
}